// round 4
// baseline (speedup 1.0000x reference)
#include <cuda_runtime.h>

// ---------------------------------------------------------------------------
// DecGreenNet_product_CP3 — algebraically collapsed:
//   out[i] = c + sum_h v[h] * tanh(x_i . Wx1[:,h] + bx1[h])
//   s_br = (sum_n y_n h_n) @ Wq2_br + (sum_n y_n) * bq2_br
//   rhs[b,d,f] = sum_x s0[b,x] s1[d,x] s2[f,x];  v = Wx2 @ rhs;  c = bx2 . rhs
// ---------------------------------------------------------------------------

#define PI_F 3.14159265358979323846f

__device__ float g_part[3][64][128];   // per-branch per-block weighted-tanh sums
__device__ float g_party[3][64];       // per-branch per-block sum of y
__device__ float g_v[512];
__device__ float g_c;

__device__ __forceinline__ float tanh_mufu(float x) {
    float y;
    asm("tanh.approx.f32 %0, %1;" : "=f"(y) : "f"(x));
    return y;
}

// accurate-enough tanh (~1e-6 abs err) from 2 MUFU ops — branch path only,
// where 8192-term sums could amplify tanh.approx's 1.5e-4 error.
__device__ __forceinline__ float tanh_acc(float z) {
    float e = __expf(2.0f * z);                 // mul + ex2
    return 1.0f - __fdividef(2.0f, e + 1.0f);   // rcp path + fma
}

// ---------------------------------------------------------------------------
// Kernel A: branch partials.  grid (64, 3) x 256 threads.
// thread (j = t&127, half = t>>7) accumulates 64 nodes; halves reduced in smem.
// ---------------------------------------------------------------------------
__global__ void __launch_bounds__(256) kernelA(
        const float* __restrict__ q0, const float* __restrict__ q1,
        const float* __restrict__ q2,
        const float* __restrict__ w0, const float* __restrict__ w1,
        const float* __restrict__ w2,
        const float* __restrict__ c0, const float* __restrict__ c1,
        const float* __restrict__ c2,
        const float* __restrict__ eq)
{
    const int br = blockIdx.y;
    const float* qx = (br == 0) ? q0 : ((br == 1) ? q1 : q2);
    const float* W1 = (br == 0) ? w0 : ((br == 1) ? w1 : w2);
    const float* B1 = (br == 0) ? c0 : ((br == 1) ? c1 : c2);

    __shared__ float sq[128];
    __shared__ float sy[128];
    __shared__ float pacc[128];

    const int t    = threadIdx.x;
    const int j    = t & 127;
    const int half = t >> 7;

    if (t < 128) {
        const float pe = PI_F * eq[0];
        const float q  = qx[blockIdx.x * 128 + t];
        sq[t] = q;
        sy[t] = sinf(pe * q);
    }
    __syncthreads();

    const float w = W1[j];
    const float b = B1[j];
    const int   n0 = half * 64;
    float acc = 0.f;
#pragma unroll 8
    for (int n = n0; n < n0 + 64; n++) {
        acc = fmaf(sy[n], tanh_acc(fmaf(sq[n], w, b)), acc);
    }

    if (half == 1) pacc[j] = acc;
    __syncthreads();
    if (half == 0) g_part[br][blockIdx.x][j] = acc + pacc[j];

    if (t == 0) {
        float s = 0.f;
#pragma unroll 8
        for (int n = 0; n < 128; n++) s += sy[n];
        g_party[br][blockIdx.x] = s;
    }
}

// ---------------------------------------------------------------------------
// Kernel B (fused B+V): one block, 1024 threads.
//  1) reduce partials -> wh[3][128], sumy[3]
//  2) s[br][j2] = wh[br] @ Wq2 + sumy[br]*bq2
//  3) rhs (smem only) + c = bx2 . rhs
//  4) v = Wx2 @ rhs  (warp-per-row, 32 warps x 16 rows)
// ---------------------------------------------------------------------------
__global__ void __launch_bounds__(1024) kernelB(
        const float* __restrict__ Wq02, const float* __restrict__ bq02,
        const float* __restrict__ Wq12, const float* __restrict__ bq12,
        const float* __restrict__ Wq22, const float* __restrict__ bq22,
        const float* __restrict__ bx2,  const float* __restrict__ Wx2)
{
    __shared__ float wh[3][128];
    __shared__ float sumy[3];
    __shared__ float s_sh[3][128];
    __shared__ __align__(16) float rsh[512];   // read as float4 in phase 4
    __shared__ __align__(16) float red[512];

    const int t = threadIdx.x;

    // phase 1: reduce per-block partials
    if (t < 384) {
        const int br = t >> 7, j = t & 127;
        float a = 0.f;
#pragma unroll 8
        for (int blk = 0; blk < 64; blk++) a += g_part[br][blk][j];
        wh[br][j] = a;
    } else if (t < 387) {
        const int br = t - 384;
        float s = 0.f;
#pragma unroll 8
        for (int blk = 0; blk < 64; blk++) s += g_party[br][blk];
        sumy[br] = s;
    }
    __syncthreads();

    // phase 2: s_br = wh_br @ Wq2_br + sumy_br * bq2_br
    if (t < 384) {
        const int br = t >> 7, j2 = t & 127;
        const float* W2 = (br == 0) ? Wq02 : ((br == 1) ? Wq12 : Wq22);
        const float* B2 = (br == 0) ? bq02 : ((br == 1) ? bq12 : bq22);
        float a = sumy[br] * B2[j2];
#pragma unroll 8
        for (int j = 0; j < 128; j++) a = fmaf(wh[br][j], W2[j * 128 + j2], a);
        s_sh[br][j2] = a;                  // j2 = b*16 + x
    }
    __syncthreads();

    // phase 3: rhs + c
    if (t < 512) {
        const int b = t >> 6, d = (t >> 3) & 7, f = t & 7;
        float r = 0.f;
#pragma unroll
        for (int x = 0; x < 16; x++)
            r += s_sh[0][b * 16 + x] * s_sh[1][d * 16 + x] * s_sh[2][f * 16 + x];
        rsh[t] = r;
        red[t] = bx2[t] * r;
    }
    __syncthreads();
    for (int off = 256; off > 0; off >>= 1) {
        if (t < off) red[t] += red[t + off];
        __syncthreads();
    }
    if (t == 0) g_c = red[0];

    // phase 4: v[h] = Wx2[h,:] . rhs  (warp per row; 16 rows per warp)
    const int wp   = t >> 5;
    const int lane = t & 31;
    const float4* r4 = (const float4*)rsh;
#pragma unroll 2
    for (int rr = 0; rr < 16; rr++) {
        const int h = wp * 16 + rr;
        const float4* row4 = (const float4*)(Wx2 + h * 512);
        float a = 0.f;
#pragma unroll
        for (int k = lane; k < 128; k += 32) {
            const float4 wv = row4[k];
            const float4 rv = r4[k];
            a = fmaf(wv.x, rv.x, fmaf(wv.y, rv.y, fmaf(wv.z, rv.z, fmaf(wv.w, rv.w, a))));
        }
#pragma unroll
        for (int o = 16; o; o >>= 1) a += __shfl_xor_sync(0xffffffffu, a, o);
        if (lane == 0) g_v[h] = a;
    }
}

// ---------------------------------------------------------------------------
// Kernel C: main batch.  128 threads = 16 rowgroups(x4 rows) x 8 h-splits.
// Per thread: 64 iters of (LDS.128 + LDS + 4x(dot3 + tanh.approx + acc)).
// Smem traffic amortized 4x vs R2 (was the binding constraint at L1=58%).
// grid = Bn/64 = 1024 blocks -> ~7 blocks/SM, ~99% wave balance.
// ---------------------------------------------------------------------------
__global__ void __launch_bounds__(128) kernelC(const float* __restrict__ X,
                                               const float* __restrict__ Wx1,
                                               const float* __restrict__ bx1,
                                               float* __restrict__ out, int Bn)
{
    __shared__ float4 wt[512];    // {Wx1[0,h], Wx1[1,h], Wx1[2,h], bx1[h]}
    __shared__ float  vs[512];
    __shared__ float4 pp[8][16];  // [h-split][rowgroup] partial accs

    const int t = threadIdx.x;
#pragma unroll
    for (int h = t; h < 512; h += 128) {
        wt[h] = make_float4(Wx1[h], Wx1[512 + h], Wx1[1024 + h], bx1[h]);
        vs[h] = g_v[h];
    }
    __syncthreads();

    const int rg = t & 15;
    const int hs = t >> 4;        // 0..7
    const int h0 = hs << 6;
    const int i0 = blockIdx.x * 64 + rg * 4;

    float r0x = 0.f, r0y = 0.f, r0z = 0.f;
    float r1x = 0.f, r1y = 0.f, r1z = 0.f;
    float r2x = 0.f, r2y = 0.f, r2z = 0.f;
    float r3x = 0.f, r3y = 0.f, r3z = 0.f;
    if (i0 + 3 < Bn) {
        // i0 is a multiple of 4 -> byte offset i0*12 is 16B-aligned
        const float4* xp = (const float4*)(X + i0 * 3);
        const float4 xa = xp[0], xb = xp[1], xc = xp[2];
        r0x = xa.x; r0y = xa.y; r0z = xa.z;
        r1x = xa.w; r1y = xb.x; r1z = xb.y;
        r2x = xb.z; r2y = xb.w; r2z = xc.x;
        r3x = xc.y; r3y = xc.z; r3z = xc.w;
    } else if (i0 < Bn) {
        const float* xs = X + i0 * 3;
        const int nr = Bn - i0;
        r0x = xs[0]; r0y = xs[1]; r0z = xs[2];
        if (nr > 1) { r1x = xs[3]; r1y = xs[4]; r1z = xs[5]; }
        if (nr > 2) { r2x = xs[6]; r2y = xs[7]; r2z = xs[8]; }
    }

    float a0 = 0.f, a1 = 0.f, a2 = 0.f, a3 = 0.f;
#pragma unroll 4
    for (int hh = 0; hh < 64; hh++) {
        const float4 w  = wt[h0 + hh];
        const float  vv = vs[h0 + hh];
        const float z0 = fmaf(r0z, w.z, fmaf(r0y, w.y, fmaf(r0x, w.x, w.w)));
        const float z1 = fmaf(r1z, w.z, fmaf(r1y, w.y, fmaf(r1x, w.x, w.w)));
        const float z2 = fmaf(r2z, w.z, fmaf(r2y, w.y, fmaf(r2x, w.x, w.w)));
        const float z3 = fmaf(r3z, w.z, fmaf(r3y, w.y, fmaf(r3x, w.x, w.w)));
        a0 = fmaf(vv, tanh_mufu(z0), a0);
        a1 = fmaf(vv, tanh_mufu(z1), a1);
        a2 = fmaf(vv, tanh_mufu(z2), a2);
        a3 = fmaf(vv, tanh_mufu(z3), a3);
    }
    pp[hs][rg] = make_float4(a0, a1, a2, a3);   // STS.128, conflict-free
    __syncthreads();

    if (t < 64) {
        const int org = t >> 2, oc = t & 3;
        float s = g_c;
#pragma unroll
        for (int h2 = 0; h2 < 8; h2++) {
            const float* pf = (const float*)&pp[h2][org];
            s += pf[oc];
        }
        const int oi = blockIdx.x * 64 + org * 4 + oc;
        if (oi < Bn) out[oi] = s;
    }
}

// ---------------------------------------------------------------------------
extern "C" void kernel_launch(void* const* d_in, const int* in_sizes, int n_in,
                              void* d_out, int out_size)
{
    const float* input = (const float*)d_in[0];
    const float* eq    = (const float*)d_in[1];
    const float* q0    = (const float*)d_in[2];
    const float* q1    = (const float*)d_in[3];
    const float* q2    = (const float*)d_in[4];
    const float* Wx1   = (const float*)d_in[5];
    const float* bx1   = (const float*)d_in[6];
    const float* Wx2   = (const float*)d_in[7];
    const float* bx2   = (const float*)d_in[8];
    const float* Wq01  = (const float*)d_in[9];
    const float* bq01  = (const float*)d_in[10];
    const float* Wq02  = (const float*)d_in[11];
    const float* bq02  = (const float*)d_in[12];
    const float* Wq11  = (const float*)d_in[13];
    const float* bq11  = (const float*)d_in[14];
    const float* Wq12  = (const float*)d_in[15];
    const float* bq12  = (const float*)d_in[16];
    const float* Wq21  = (const float*)d_in[17];
    const float* bq21  = (const float*)d_in[18];
    const float* Wq22  = (const float*)d_in[19];
    const float* bq22  = (const float*)d_in[20];

    const int N  = in_sizes[2];          // 8192 quad nodes
    const int Bn = in_sizes[0] / 3;      // 65536 rows
    const int nblkA = N / 128;           // 64

    kernelA<<<dim3(nblkA, 3), 256>>>(q0, q1, q2,
                                     Wq01, Wq11, Wq21,
                                     bq01, bq11, bq21, eq);
    kernelB<<<1, 1024>>>(Wq02, bq02, Wq12, bq12, Wq22, bq22, bx2, Wx2);
    kernelC<<<(Bn + 63) / 64, 128>>>(input, Wx1, bx1, (float*)d_out, Bn);
}

// round 5
// speedup vs baseline: 1.3315x; 1.3315x over previous
#include <cuda_runtime.h>

// ---------------------------------------------------------------------------
// DecGreenNet_product_CP3 — algebraically collapsed:
//   out[i] = c + sum_h v[h] * tanh(x_i . Wx1[:,h] + bx1[h])
//   s_br = (sum_n y_n h_n) @ Wq2_br + (sum_n y_n) * bq2_br
//   rhs[b,d,f] = sum_x s0[b,x] s1[d,x] s2[f,x];  v = Wx2 @ rhs;  c = bx2 . rhs
// ---------------------------------------------------------------------------

#define PI_F 3.14159265358979323846f

__device__ float g_part[3][64][128];   // per-branch per-block weighted-tanh sums
__device__ float g_party[3][64];       // per-branch per-block sum of y
__device__ __align__(16) float g_rhs[512];
__device__ float g_v[512];
__device__ float g_c;

__device__ __forceinline__ float tanh_mufu(float x) {
    float y;
    asm("tanh.approx.f32 %0, %1;" : "=f"(y) : "f"(x));
    return y;
}

// accurate-enough tanh (~1e-6 abs err) from 2 MUFU ops — branch path only,
// where 8192-term sums could amplify tanh.approx's 1.5e-4 error.
__device__ __forceinline__ float tanh_acc(float z) {
    float e = __expf(2.0f * z);                 // mul + ex2
    return 1.0f - __fdividef(2.0f, e + 1.0f);   // rcp path + fma
}

// ---------------------------------------------------------------------------
// Kernel A: branch partials.  grid (64, 3) x 1024 threads.
// thread (j = t&127, grp = t>>7) accumulates 16 nodes; 8 groups reduced in smem.
// 6144 warps chip-wide (65% occ) — 4x the parallelism of the R4 version whose
// 64-deep dependent MUFU chain at 13% occ was latency-bound (7.4us vs 1.5 floor).
// ---------------------------------------------------------------------------
__global__ void __launch_bounds__(1024) kernelA(
        const float* __restrict__ q0, const float* __restrict__ q1,
        const float* __restrict__ q2,
        const float* __restrict__ w0, const float* __restrict__ w1,
        const float* __restrict__ w2,
        const float* __restrict__ c0, const float* __restrict__ c1,
        const float* __restrict__ c2,
        const float* __restrict__ eq)
{
    const int br = blockIdx.y;
    const float* qx = (br == 0) ? q0 : ((br == 1) ? q1 : q2);
    const float* W1 = (br == 0) ? w0 : ((br == 1) ? w1 : w2);
    const float* B1 = (br == 0) ? c0 : ((br == 1) ? c1 : c2);

    __shared__ float sq[128];
    __shared__ float sy[128];
    __shared__ float pacc[8][128];

    const int t   = threadIdx.x;
    const int j   = t & 127;
    const int grp = t >> 7;           // 0..7

    if (t < 128) {
        const float pe = PI_F * eq[0];
        const float q  = qx[blockIdx.x * 128 + t];
        sq[t] = q;
        sy[t] = sinf(pe * q);
    }
    __syncthreads();

    const float w  = W1[j];
    const float b  = B1[j];
    const int   n0 = grp * 16;
    float acc = 0.f;
#pragma unroll
    for (int n = n0; n < n0 + 16; n++) {
        acc = fmaf(sy[n], tanh_acc(fmaf(sq[n], w, b)), acc);
    }
    pacc[grp][j] = acc;

    // warp 4 (t 128..159) reduces sum_y while others sync
    if (t >= 128 && t < 160) {
        const int lane = t - 128;
        float s = sy[lane * 4] + sy[lane * 4 + 1] + sy[lane * 4 + 2] + sy[lane * 4 + 3];
#pragma unroll
        for (int o = 16; o; o >>= 1) s += __shfl_xor_sync(0xffffffffu, s, o);
        if (lane == 0) g_party[br][blockIdx.x] = s;
    }
    __syncthreads();

    if (t < 128) {
        float s = 0.f;
#pragma unroll
        for (int g = 0; g < 8; g++) s += pacc[g][t];
        g_part[br][blockIdx.x][t] = s;
    }
}

// ---------------------------------------------------------------------------
// Kernel B: one block, 512 threads.  reduce partials -> s[br] -> rhs, c.
// (V deliberately NOT fused: its 1MB Wx2 stream must not serialize on 1 SM.)
// ---------------------------------------------------------------------------
__global__ void kernelB(const float* __restrict__ Wq02, const float* __restrict__ bq02,
                        const float* __restrict__ Wq12, const float* __restrict__ bq12,
                        const float* __restrict__ Wq22, const float* __restrict__ bq22,
                        const float* __restrict__ bx2)
{
    __shared__ float wh[3][128];
    __shared__ float sumy[3];
    __shared__ float s_sh[3][128];
    __shared__ float red[512];

    const int t = threadIdx.x;

    if (t < 384) {
        const int br = t >> 7, j = t & 127;
        float a = 0.f;
#pragma unroll 8
        for (int blk = 0; blk < 64; blk++) a += g_part[br][blk][j];
        wh[br][j] = a;
    } else if (t < 387) {
        const int br = t - 384;
        float s = 0.f;
#pragma unroll 8
        for (int blk = 0; blk < 64; blk++) s += g_party[br][blk];
        sumy[br] = s;
    }
    __syncthreads();

    if (t < 384) {
        const int br = t >> 7, j2 = t & 127;
        const float* W2 = (br == 0) ? Wq02 : ((br == 1) ? Wq12 : Wq22);
        const float* B2 = (br == 0) ? bq02 : ((br == 1) ? bq12 : bq22);
        float a = sumy[br] * B2[j2];
#pragma unroll 8
        for (int j = 0; j < 128; j++) a = fmaf(wh[br][j], W2[j * 128 + j2], a);
        s_sh[br][j2] = a;                  // j2 = b*16 + x
    }
    __syncthreads();

    const int k = t;
    const int b = k >> 6, d = (k >> 3) & 7, f = k & 7;
    float r = 0.f;
#pragma unroll
    for (int x = 0; x < 16; x++)
        r += s_sh[0][b * 16 + x] * s_sh[1][d * 16 + x] * s_sh[2][f * 16 + x];
    g_rhs[k] = r;

    red[t] = bx2[k] * r;
    __syncthreads();
    for (int off = 256; off > 0; off >>= 1) {
        if (t < off) red[t] += red[t + off];
        __syncthreads();
    }
    if (t == 0) g_c = red[0];
}

// ---------------------------------------------------------------------------
// Kernel V: v[h] = Wx2[h,:] . rhs.  grid 64 x 256; warp per row, float4 loads.
// ---------------------------------------------------------------------------
__global__ void __launch_bounds__(256) kernelV(const float* __restrict__ Wx2)
{
    __shared__ float4 rsh[128];
    const int t = threadIdx.x;
    if (t < 128) rsh[t] = ((const float4*)g_rhs)[t];
    __syncthreads();

    const int h    = blockIdx.x * 8 + (t >> 5);
    const int lane = t & 31;
    const float4* row4 = (const float4*)(Wx2 + h * 512);
    float a = 0.f;
#pragma unroll
    for (int k = lane; k < 128; k += 32) {
        const float4 w = row4[k];
        const float4 r = rsh[k];
        a = fmaf(w.x, r.x, fmaf(w.y, r.y, fmaf(w.z, r.z, fmaf(w.w, r.w, a))));
    }
#pragma unroll
    for (int o = 16; o; o >>= 1) a += __shfl_xor_sync(0xffffffffu, a, o);
    if (lane == 0) g_v[h] = a;
}

// ---------------------------------------------------------------------------
// Kernel C: main batch.  256 threads = 16 rowgroups(x4 rows) x 16 h-splits(x32 h).
// Per thread: 32 iters of (LDS.128 + LDS + 4x(dot3 + tanh.approx + acc)).
// Smem traffic amortized 4x over rows; grid 1024 x 8 warps -> 56 warps/SM (87%).
// ---------------------------------------------------------------------------
__global__ void __launch_bounds__(256) kernelC(const float* __restrict__ X,
                                               const float* __restrict__ Wx1,
                                               const float* __restrict__ bx1,
                                               float* __restrict__ out, int Bn)
{
    __shared__ float4 wt[512];     // {Wx1[0,h], Wx1[1,h], Wx1[2,h], bx1[h]}
    __shared__ float  vs[512];
    __shared__ float4 pp[16][16];  // [h-split][rowgroup] partial accs

    const int t = threadIdx.x;
#pragma unroll
    for (int h = t; h < 512; h += 256) {
        wt[h] = make_float4(Wx1[h], Wx1[512 + h], Wx1[1024 + h], bx1[h]);
        vs[h] = g_v[h];
    }
    __syncthreads();

    const int rg = t & 15;
    const int hs = t >> 4;        // 0..15
    const int h0 = hs << 5;       // 32 h per split
    const int i0 = blockIdx.x * 64 + rg * 4;

    float r0x = 0.f, r0y = 0.f, r0z = 0.f;
    float r1x = 0.f, r1y = 0.f, r1z = 0.f;
    float r2x = 0.f, r2y = 0.f, r2z = 0.f;
    float r3x = 0.f, r3y = 0.f, r3z = 0.f;
    if (i0 + 3 < Bn) {
        // i0 is a multiple of 4 -> byte offset i0*12 is 16B-aligned
        const float4* xp = (const float4*)(X + i0 * 3);
        const float4 xa = xp[0], xb = xp[1], xc = xp[2];
        r0x = xa.x; r0y = xa.y; r0z = xa.z;
        r1x = xa.w; r1y = xb.x; r1z = xb.y;
        r2x = xb.z; r2y = xb.w; r2z = xc.x;
        r3x = xc.y; r3y = xc.z; r3z = xc.w;
    } else if (i0 < Bn) {
        const float* xs = X + i0 * 3;
        const int nr = Bn - i0;
        r0x = xs[0]; r0y = xs[1]; r0z = xs[2];
        if (nr > 1) { r1x = xs[3]; r1y = xs[4]; r1z = xs[5]; }
        if (nr > 2) { r2x = xs[6]; r2y = xs[7]; r2z = xs[8]; }
    }

    float a0 = 0.f, a1 = 0.f, a2 = 0.f, a3 = 0.f;
#pragma unroll 4
    for (int hh = 0; hh < 32; hh++) {
        const float4 w  = wt[h0 + hh];
        const float  vv = vs[h0 + hh];
        const float z0 = fmaf(r0z, w.z, fmaf(r0y, w.y, fmaf(r0x, w.x, w.w)));
        const float z1 = fmaf(r1z, w.z, fmaf(r1y, w.y, fmaf(r1x, w.x, w.w)));
        const float z2 = fmaf(r2z, w.z, fmaf(r2y, w.y, fmaf(r2x, w.x, w.w)));
        const float z3 = fmaf(r3z, w.z, fmaf(r3y, w.y, fmaf(r3x, w.x, w.w)));
        a0 = fmaf(vv, tanh_mufu(z0), a0);
        a1 = fmaf(vv, tanh_mufu(z1), a1);
        a2 = fmaf(vv, tanh_mufu(z2), a2);
        a3 = fmaf(vv, tanh_mufu(z3), a3);
    }
    pp[hs][rg] = make_float4(a0, a1, a2, a3);   // STS.128, conflict-free
    __syncthreads();

    if (t < 64) {
        const float* pf = (const float*)pp;     // pf[h2*64 + local_row]
        float s = g_c;
#pragma unroll
        for (int h2 = 0; h2 < 16; h2++) s += pf[h2 * 64 + t];
        const int oi = blockIdx.x * 64 + t;
        if (oi < Bn) out[oi] = s;
    }
}

// ---------------------------------------------------------------------------
extern "C" void kernel_launch(void* const* d_in, const int* in_sizes, int n_in,
                              void* d_out, int out_size)
{
    const float* input = (const float*)d_in[0];
    const float* eq    = (const float*)d_in[1];
    const float* q0    = (const float*)d_in[2];
    const float* q1    = (const float*)d_in[3];
    const float* q2    = (const float*)d_in[4];
    const float* Wx1   = (const float*)d_in[5];
    const float* bx1   = (const float*)d_in[6];
    const float* Wx2   = (const float*)d_in[7];
    const float* bx2   = (const float*)d_in[8];
    const float* Wq01  = (const float*)d_in[9];
    const float* bq01  = (const float*)d_in[10];
    const float* Wq02  = (const float*)d_in[11];
    const float* bq02  = (const float*)d_in[12];
    const float* Wq11  = (const float*)d_in[13];
    const float* bq11  = (const float*)d_in[14];
    const float* Wq12  = (const float*)d_in[15];
    const float* bq12  = (const float*)d_in[16];
    const float* Wq21  = (const float*)d_in[17];
    const float* bq21  = (const float*)d_in[18];
    const float* Wq22  = (const float*)d_in[19];
    const float* bq22  = (const float*)d_in[20];

    const int N  = in_sizes[2];          // 8192 quad nodes
    const int Bn = in_sizes[0] / 3;      // 65536 rows
    const int nblkA = N / 128;           // 64

    kernelA<<<dim3(nblkA, 3), 1024>>>(q0, q1, q2,
                                      Wq01, Wq11, Wq21,
                                      bq01, bq11, bq21, eq);
    kernelB<<<1, 512>>>(Wq02, bq02, Wq12, bq12, Wq22, bq22, bx2);
    kernelV<<<64, 256>>>(Wx2);
    kernelC<<<(Bn + 63) / 64, 256>>>(input, Wx1, bx1, (float*)d_out, Bn);
}